// round 12
// baseline (speedup 1.0000x reference)
#include <cuda_runtime.h>
#include <cuda_fp16.h>
#include <cstdint>

#define NPTS   256
#define NHEAD  8
#define HID    64
#define TPB    128
#define WARPS  4
#define TILES  2            // 32-pixel tiles per warp
#define CTA_PIX (WARPS * TILES * 32)   // 256

#define ROW_STRIDE 48       // bytes per staged pixel row (conflict-free ldmatrix phases)
#define WARP_SMEM  (32 * ROW_STRIDE)   // single fp16 plane

__device__ __forceinline__ uint32_t smem_u32(const void* p) {
    uint32_t a;
    asm("{ .reg .u64 t; cvta.to.shared.u64 t, %1; cvt.u32.u64 %0, t; }" : "=r"(a) : "l"(p));
    return a;
}
__device__ __forceinline__ void ldm_x4(uint32_t* r, uint32_t addr) {
    asm volatile("ldmatrix.sync.aligned.m8n8.x4.shared.b16 {%0,%1,%2,%3}, [%4];"
                 : "=r"(r[0]), "=r"(r[1]), "=r"(r[2]), "=r"(r[3]) : "r"(addr));
}
// accumulate form: D += A*B (C tied to D)
__device__ __forceinline__ void mma_f16(float* d, const uint32_t* a, const uint32_t* b) {
    asm volatile("mma.sync.aligned.m16n8k16.row.col.f32.f16.f16.f32 "
                 "{%0,%1,%2,%3}, {%4,%5,%6,%7}, {%8,%9}, {%0,%1,%2,%3};"
                 : "+f"(d[0]), "+f"(d[1]), "+f"(d[2]), "+f"(d[3])
                 : "r"(a[0]), "r"(a[1]), "r"(a[2]), "r"(a[3]), "r"(b[0]), "r"(b[1]));
}
// first-touch form: D = A*B + C with explicit persistent C quad (no re-zero MOVs)
__device__ __forceinline__ void mma_f16_c(float* d, const uint32_t* a, const uint32_t* b,
                                          const float* c) {
    asm volatile("mma.sync.aligned.m16n8k16.row.col.f32.f16.f16.f32 "
                 "{%0,%1,%2,%3}, {%4,%5,%6,%7}, {%8,%9}, {%10,%11,%12,%13};"
                 : "=f"(d[0]), "=f"(d[1]), "=f"(d[2]), "=f"(d[3])
                 : "r"(a[0]), "r"(a[1]), "r"(a[2]), "r"(a[3]), "r"(b[0]), "r"(b[1]),
                   "f"(c[0]), "f"(c[1]), "f"(c[2]), "f"(c[3]));
}
__device__ __forceinline__ uint32_t h2(float lo, float hi) {   // lo -> low half
    uint32_t r;
    asm("cvt.rn.f16x2.f32 %0, %1, %2;" : "=r"(r) : "f"(hi), "f"(lo));
    return r;
}
// packed fp16x2 silu on PRE-HALVED input hx = x/2 (W1/b1 folded):
// silu(x) = hx*tanh(hx) + hx   (2 instrs / 2 values)
__device__ __forceinline__ uint32_t silu_h2(uint32_t hx2) {
    uint32_t t, r;
    asm("tanh.approx.f16x2 %0, %1;" : "=r"(t) : "r"(hx2));
    asm("fma.rn.f16x2 %0, %1, %2, %1;" : "=r"(r) : "r"(hx2), "r"(t));
    return r;
}
__device__ __forceinline__ float tanh_fast(float x) {
    float r; asm("tanh.approx.f32 %0, %1;" : "=f"(r) : "f"(x)); return r;
}
__device__ __forceinline__ float sqrt_fast(float x) {
    float r; asm("sqrt.approx.ftz.f32 %0, %1;" : "=f"(r) : "f"(x)); return r;
}
__device__ __forceinline__ float rcp_fast(float x) {
    float r; asm("rcp.approx.ftz.f32 %0, %1;" : "=f"(r) : "f"(x)); return r;
}

__device__ __forceinline__ void compute_features(float4 f, float* o) {
    float rx = f.x, ry = f.y, rvx = f.z, rvy = f.w;
    float d2    = fmaf(rx, rx, ry * ry);
    float dist  = sqrt_fast(d2 + 1e-6f);
    float invde = rcp_fast(dist + 1e-6f);
    float invd  = rcp_fast(dist + 0.1f);
    float ssq   = fmaf(rvx, rvx, rvy * rvy);
    float rsp   = sqrt_fast(ssq + 1e-6f);
    float dot   = fmaf(rvx, rx, rvy * ry);
    float closing = dot * invde;
    float ttca  = tanh_fast(-dot * rcp_fast(ssq + 1e-6f));
    o[0]  = rx;       o[1]  = ry;       o[2]  = rvx;      o[3]  = rvy;
    o[4]  = dist;     o[5]  = invd;     o[6]  = rsp;      o[7]  = closing;
    o[8]  = rx * invde; o[9] = ry * invde; o[10] = ttca;  o[11] = dot;
}

__global__ void __launch_bounds__(TPB, 7)
relfeat_hmma_kernel(const float* __restrict__ ff,
                    const float* __restrict__ W1,
                    const float* __restrict__ b1,
                    const float* __restrict__ W2,
                    const float* __restrict__ b2,
                    float* __restrict__ out) {
    __shared__ __align__(16) char stage[WARPS * WARP_SMEM];

    const int tid  = threadIdx.x;
    const int wid  = tid >> 5;
    const int lane = tid & 31;
    const int q    = lane & 3;        // quad col index
    const int g    = lane >> 2;       // row group

    const uint32_t warpBase = smem_u32(stage) + wid * WARP_SMEM;

    const int gw = blockIdx.x * WARPS + wid;   // global warp id
    const float4* ffp = reinterpret_cast<const float4*>(ff);

    // ---- prefetch ALL tile inputs up front (one DRAM exposure) ----
    float4 raw[TILES];
    #pragma unroll
    for (int it = 0; it < TILES; it++)
        raw[it] = ffp[gw * (TILES * 32) + it * 32 + lane];

    // ---------- weights -> fp16 register fragments ----------
    // Layer1 B: B1[k][n] = 0.5*W1[k][n] (0.5 folded; silu consumes x/2),
    // k: 0..11 = W1 rows, 12 = 0.5*b1, 13..15 = 0
    uint32_t w1[8][2];
    #pragma unroll
    for (int t = 0; t < 8; t++) {
        int n = t * 8 + g;
        int k0 = 2 * q, k2 = 2 * q + 8;
        float v0 = 0.5f * W1[k0 * HID + n];
        float v1 = 0.5f * W1[(k0 + 1) * HID + n];
        float v2 = (k2 < 12) ? 0.5f * W1[k2 * HID + n] : (k2 == 12 ? 0.5f * b1[n] : 0.0f);
        float v3 = (k2 + 1 < 12) ? 0.5f * W1[(k2 + 1) * HID + n] : 0.0f;
        w1[t][0] = h2(v0, v1);
        w1[t][1] = h2(v2, v3);
    }
    // Layer2 B: B2[k][o] = W2[k*8+o]  (unchanged)
    uint32_t w2[4][2];
    #pragma unroll
    for (int kt = 0; kt < 4; kt++) {
        int o = g;
        int k0 = 16 * kt + 2 * q;
        w2[kt][0] = h2(W2[k0 * NHEAD + o],       W2[(k0 + 1) * NHEAD + o]);
        w2[kt][1] = h2(W2[(k0 + 8) * NHEAD + o], W2[(k0 + 9) * NHEAD + o]);
    }
    // persistent C quads: zeros and b2-bias (match D layout rows g/g+8)
    float zq[4] = {0.0f, 0.0f, 0.0f, 0.0f};
    float bq[4];
    bq[0] = b2[2 * q]; bq[1] = b2[2 * q + 1]; bq[2] = bq[0]; bq[3] = bq[1];

    // ldmatrix row address for this lane (within a 16-row mtile)
    const int lt = lane >> 3, lr = lane & 7;
    const uint32_t ldmOff = (uint32_t)(((lt & 1) * 8 + lr) * ROW_STRIDE + (lt >> 1) * 16);

    #pragma unroll
    for (int it = 0; it < TILES; it++) {
        const int pixBase = gw * (TILES * 32) + it * 32;

        // ---- features for this lane's pixel -> 16 fp16 per row in SMEM ----
        {
            float f[12];
            compute_features(raw[it], f);
            uint32_t h8[8];
            #pragma unroll
            for (int c = 0; c < 6; c++) h8[c] = h2(f[2 * c], f[2 * c + 1]);
            h8[6] = 0x00003C00u;   // k=12: fp16 1.0 (bias lane), k=13: 0
            h8[7] = 0;             // k=14,15
            __syncwarp();
            char* row = stage + wid * WARP_SMEM + lane * ROW_STRIDE;
            *reinterpret_cast<uint4*>(row)      = make_uint4(h8[0], h8[1], h8[2], h8[3]);
            *reinterpret_cast<uint4*>(row + 16) = make_uint4(h8[4], h8[5], h8[6], h8[7]);
            __syncwarp();
        }

        #pragma unroll
        for (int mt = 0; mt < 2; mt++) {
            // ---- A fragment via ldmatrix ----
            uint32_t a[4];
            ldm_x4(a, warpBase + (uint32_t)(mt * 16 * ROW_STRIDE) + ldmOff);

            // ---- fused layer1 -> fp16x2 SiLU -> layer2 (no re-zero MOVs) ----
            float dd0[4], dd1[4];
            #pragma unroll
            for (int kt = 0; kt < 4; kt++) {
                float d0[4], d1[4];
                mma_f16_c(d0, a, w1[2 * kt],     zq);   // d = x/2
                mma_f16_c(d1, a, w1[2 * kt + 1], zq);
                uint32_t a2[4];
                a2[0] = silu_h2(h2(d0[0], d0[1]));
                a2[1] = silu_h2(h2(d0[2], d0[3]));
                a2[2] = silu_h2(h2(d1[0], d1[1]));
                a2[3] = silu_h2(h2(d1[2], d1[3]));
                if (kt == 0)      mma_f16_c(dd0, a2, w2[0], bq);  // b2 folded in
                else if (kt == 1) mma_f16_c(dd1, a2, w2[1], zq);
                else if (kt == 2) mma_f16(dd0, a2, w2[2]);
                else              mma_f16(dd1, a2, w2[3]);
            }
            // ---- store transposed (B, H, N, N) ----
            int p0 = pixBase + mt * 16;
            int m = p0 & (NPTS - 1);
            int n = (p0 >> 8) & (NPTS - 1);
            int b = p0 >> 16;
            int base = b * (NHEAD * NPTS * NPTS) + n * NPTS + m;
            int c0 = (2 * q) * (NPTS * NPTS), c1 = (2 * q + 1) * (NPTS * NPTS);
            out[base + c0 + g]     = dd0[0] + dd1[0];
            out[base + c1 + g]     = dd0[1] + dd1[1];
            out[base + c0 + g + 8] = dd0[2] + dd1[2];
            out[base + c1 + g + 8] = dd0[3] + dd1[3];
        }
    }
}

extern "C" void kernel_launch(void* const* d_in, const int* in_sizes, int n_in,
                              void* d_out, int out_size) {
    const float* ff = (const float*)d_in[0];
    const float* W1 = (const float*)d_in[1];
    const float* b1 = (const float*)d_in[2];
    const float* W2 = (const float*)d_in[3];
    const float* b2 = (const float*)d_in[4];
    float* out = (float*)d_out;

    int pixels = out_size / NHEAD;        // 1,048,576
    int blocks = pixels / CTA_PIX;        // 4096
    relfeat_hmma_kernel<<<blocks, TPB>>>(ff, W1, b1, W2, b2, out);
}

// round 13
// speedup vs baseline: 1.1429x; 1.1429x over previous
#include <cuda_runtime.h>
#include <cuda_fp16.h>
#include <cstdint>

#define NPTS   256
#define NHEAD  8
#define HID    64
#define TPB    128
#define WARPS  4
#define TILES  2            // 32-pixel tiles per warp
#define CTA_PIX (WARPS * TILES * 32)   // 256

#define ROW_STRIDE 48       // bytes per staged pixel row (conflict-free ldmatrix phases)
#define WARP_SMEM  (32 * ROW_STRIDE)   // single fp16 plane
#define OUT_STRIDE 36       // floats per head row in out-stage (conflict-free STS+LDS)

__device__ __forceinline__ uint32_t smem_u32(const void* p) {
    uint32_t a;
    asm("{ .reg .u64 t; cvta.to.shared.u64 t, %1; cvt.u32.u64 %0, t; }" : "=r"(a) : "l"(p));
    return a;
}
__device__ __forceinline__ void ldm_x4(uint32_t* r, uint32_t addr) {
    asm volatile("ldmatrix.sync.aligned.m8n8.x4.shared.b16 {%0,%1,%2,%3}, [%4];"
                 : "=r"(r[0]), "=r"(r[1]), "=r"(r[2]), "=r"(r[3]) : "r"(addr));
}
__device__ __forceinline__ void mma_f16(float* d, const uint32_t* a, const uint32_t* b) {
    asm volatile("mma.sync.aligned.m16n8k16.row.col.f32.f16.f16.f32 "
                 "{%0,%1,%2,%3}, {%4,%5,%6,%7}, {%8,%9}, {%0,%1,%2,%3};"
                 : "+f"(d[0]), "+f"(d[1]), "+f"(d[2]), "+f"(d[3])
                 : "r"(a[0]), "r"(a[1]), "r"(a[2]), "r"(a[3]), "r"(b[0]), "r"(b[1]));
}
__device__ __forceinline__ uint32_t h2(float lo, float hi) {   // lo -> low half
    uint32_t r;
    asm("cvt.rn.f16x2.f32 %0, %1, %2;" : "=r"(r) : "f"(hi), "f"(lo));
    return r;
}
// packed fp16x2 silu: h = hx*tanh(hx) + hx, hx = 0.5*x  (3 instrs / 2 values)
__device__ __forceinline__ uint32_t silu_h2(uint32_t x2) {
    uint32_t hx, t, r;
    asm("mul.f16x2 %0, %1, %2;" : "=r"(hx) : "r"(x2), "r"(0x38003800u));  // 0.5 pair
    asm("tanh.approx.f16x2 %0, %1;" : "=r"(t) : "r"(hx));
    asm("fma.rn.f16x2 %0, %1, %2, %1;" : "=r"(r) : "r"(hx), "r"(t));
    return r;
}
__device__ __forceinline__ float tanh_fast(float x) {
    float r; asm("tanh.approx.f32 %0, %1;" : "=f"(r) : "f"(x)); return r;
}
__device__ __forceinline__ float sqrt_fast(float x) {
    float r; asm("sqrt.approx.ftz.f32 %0, %1;" : "=f"(r) : "f"(x)); return r;
}
__device__ __forceinline__ float rcp_fast(float x) {
    float r; asm("rcp.approx.ftz.f32 %0, %1;" : "=f"(r) : "f"(x)); return r;
}

__device__ __forceinline__ void compute_features(float4 f, float* o) {
    float rx = f.x, ry = f.y, rvx = f.z, rvy = f.w;
    float d2    = fmaf(rx, rx, ry * ry);
    float dist  = sqrt_fast(d2 + 1e-6f);
    float invde = rcp_fast(dist + 1e-6f);
    float invd  = rcp_fast(dist + 0.1f);
    float ssq   = fmaf(rvx, rvx, rvy * rvy);
    float rsp   = sqrt_fast(ssq + 1e-6f);
    float dot   = fmaf(rvx, rx, rvy * ry);
    float closing = dot * invde;
    float ttca  = tanh_fast(-dot * rcp_fast(ssq + 1e-6f));
    o[0]  = rx;       o[1]  = ry;       o[2]  = rvx;      o[3]  = rvy;
    o[4]  = dist;     o[5]  = invd;     o[6]  = rsp;      o[7]  = closing;
    o[8]  = rx * invde; o[9] = ry * invde; o[10] = ttca;  o[11] = dot;
}

__global__ void __launch_bounds__(TPB, 8)
relfeat_hmma_kernel(const float* __restrict__ ff,
                    const float* __restrict__ W1,
                    const float* __restrict__ b1,
                    const float* __restrict__ W2,
                    const float* __restrict__ b2,
                    float* __restrict__ out) {
    __shared__ __align__(16) char  stage[WARPS * WARP_SMEM];
    __shared__ __align__(16) float sout[WARPS][NHEAD * OUT_STRIDE];

    const int tid  = threadIdx.x;
    const int wid  = tid >> 5;
    const int lane = tid & 31;
    const int q    = lane & 3;        // quad col index
    const int g    = lane >> 2;       // row group

    const uint32_t warpBase = smem_u32(stage) + wid * WARP_SMEM;

    const int gw = blockIdx.x * WARPS + wid;   // global warp id
    const float4* ffp = reinterpret_cast<const float4*>(ff);

    // ---- prefetch ALL tile inputs up front (one DRAM exposure) ----
    float4 raw[TILES];
    #pragma unroll
    for (int it = 0; it < TILES; it++)
        raw[it] = ffp[gw * (TILES * 32) + it * 32 + lane];

    // ---------- weights -> fp16 register fragments ----------
    // Layer1 B: B1[k][n], k: 0..11 = W1 rows, 12 = b1, 13..15 = 0
    uint32_t w1[8][2];
    #pragma unroll
    for (int t = 0; t < 8; t++) {
        int n = t * 8 + g;
        int k0 = 2 * q, k2 = 2 * q + 8;
        float v0 = W1[k0 * HID + n];
        float v1 = W1[(k0 + 1) * HID + n];
        float v2 = (k2 < 12) ? W1[k2 * HID + n] : (k2 == 12 ? b1[n] : 0.0f);
        float v3 = (k2 + 1 < 12) ? W1[(k2 + 1) * HID + n] : 0.0f;
        w1[t][0] = h2(v0, v1);
        w1[t][1] = h2(v2, v3);
    }
    // Layer2 B: B2[k][o] = W2[k*8+o]
    uint32_t w2[4][2];
    #pragma unroll
    for (int kt = 0; kt < 4; kt++) {
        int o = g;
        int k0 = 16 * kt + 2 * q;
        w2[kt][0] = h2(W2[k0 * NHEAD + o],       W2[(k0 + 1) * NHEAD + o]);
        w2[kt][1] = h2(W2[(k0 + 8) * NHEAD + o], W2[(k0 + 9) * NHEAD + o]);
    }
    const float b2a = b2[2 * q], b2b = b2[2 * q + 1];

    // ldmatrix row address for this lane (within a 16-row mtile)
    const int lt = lane >> 3, lr = lane & 7;
    const uint32_t ldmOff = (uint32_t)(((lt & 1) * 8 + lr) * ROW_STRIDE + (lt >> 1) * 16);

    #pragma unroll
    for (int it = 0; it < TILES; it++) {
        const int pixBase = gw * (TILES * 32) + it * 32;

        // ---- features for this lane's pixel -> 16 fp16 per row in SMEM ----
        {
            float f[12];
            compute_features(raw[it], f);
            uint32_t h8[8];
            #pragma unroll
            for (int c = 0; c < 6; c++) h8[c] = h2(f[2 * c], f[2 * c + 1]);
            h8[6] = 0x00003C00u;   // k=12: fp16 1.0 (bias lane), k=13: 0
            h8[7] = 0;             // k=14,15
            __syncwarp();
            char* row = stage + wid * WARP_SMEM + lane * ROW_STRIDE;
            *reinterpret_cast<uint4*>(row)      = make_uint4(h8[0], h8[1], h8[2], h8[3]);
            *reinterpret_cast<uint4*>(row + 16) = make_uint4(h8[4], h8[5], h8[6], h8[7]);
            __syncwarp();
        }

        float* so = sout[wid];

        #pragma unroll
        for (int mt = 0; mt < 2; mt++) {
            // ---- A fragment via ldmatrix ----
            uint32_t a[4];
            ldm_x4(a, warpBase + (uint32_t)(mt * 16 * ROW_STRIDE) + ldmOff);

            // ---- fused layer1 -> cvt -> fp16x2 SiLU -> layer2 ----
            float dd0[4] = {b2a, b2b, b2a, b2b};   // b2 folded into init
            float dd1[4] = {0.0f, 0.0f, 0.0f, 0.0f};
            #pragma unroll
            for (int kt = 0; kt < 4; kt++) {
                float d0[4] = {0.0f, 0.0f, 0.0f, 0.0f};
                float d1[4] = {0.0f, 0.0f, 0.0f, 0.0f};
                mma_f16(d0, a, w1[2 * kt]);
                mma_f16(d1, a, w1[2 * kt + 1]);
                uint32_t a2[4];
                a2[0] = silu_h2(h2(d0[0], d0[1]));
                a2[1] = silu_h2(h2(d0[2], d0[3]));
                a2[2] = silu_h2(h2(d1[0], d1[1]));
                a2[3] = silu_h2(h2(d1[2], d1[3]));
                mma_f16((kt & 1) ? dd1 : dd0, a2, w2[kt]);
            }
            // ---- stage outputs into per-warp SMEM [head][m] (conflict-free) ----
            int mBase = mt * 16;
            so[(2 * q)     * OUT_STRIDE + mBase + g]     = dd0[0] + dd1[0];
            so[(2 * q + 1) * OUT_STRIDE + mBase + g]     = dd0[1] + dd1[1];
            so[(2 * q)     * OUT_STRIDE + mBase + g + 8] = dd0[2] + dd1[2];
            so[(2 * q + 1) * OUT_STRIDE + mBase + g + 8] = dd0[3] + dd1[3];
        }
        __syncwarp();

        // ---- coalesced writeback: lane -> (head o = l>>3, m4 = l&7) ----
        {
            int o  = lane >> 3;        // 0..3 (and o+4)
            int m4 = lane & 7;         // float4 index within 32 m
            float4 r0 = *reinterpret_cast<float4*>(so + o * OUT_STRIDE + m4 * 4);
            float4 r1 = *reinterpret_cast<float4*>(so + (o + 4) * OUT_STRIDE + m4 * 4);
            int m0 = pixBase & (NPTS - 1);
            int n  = (pixBase >> 8) & (NPTS - 1);
            int b  = pixBase >> 16;
            float4* op = reinterpret_cast<float4*>(out);
            int idx0 = (((b * NHEAD + o) * NPTS + n) * NPTS + m0) / 4 + m4;
            op[idx0]                      = r0;   // heads 0..3
            op[idx0 + 4 * NPTS * NPTS/4]  = r1;   // heads 4..7
        }
        __syncwarp();
    }
}

extern "C" void kernel_launch(void* const* d_in, const int* in_sizes, int n_in,
                              void* d_out, int out_size) {
    const float* ff = (const float*)d_in[0];
    const float* W1 = (const float*)d_in[1];
    const float* b1 = (const float*)d_in[2];
    const float* W2 = (const float*)d_in[3];
    const float* b2 = (const float*)d_in[4];
    float* out = (float*)d_out;

    int pixels = out_size / NHEAD;        // 1,048,576
    int blocks = pixels / CTA_PIX;        // 4096
    relfeat_hmma_kernel<<<blocks, TPB>>>(ff, W1, b1, W2, b2, out);
}